// round 10
// baseline (speedup 1.0000x reference)
#include <cuda_runtime.h>
#include <math_constants.h>

// Pooling_21577915695109: out[b,n,:] = max over m of x_pad[b, index[n,m], :]
// x: (4, 50000, 64) fp32, index: (50000, 16) int32 in [0, 50000]; idx==50000 -> zero row.
//
// R10: R7 base + (a) all 16 neighbor indices hoisted before any gather, removing
// the per-chunk idx-load serialization bubble; (b) streaming output stores
// (__stcs) so the 51 MB output stream doesn't evict the L2-resident x working set.

constexpr int N_NODES = 50000;
constexpr int M_NEIGH = 16;
constexpr int HID     = 64;

constexpr int THREADS_PER_NODE = 16;   // 16 lanes x float4 = 64 floats = one row
constexpr int NODES_PER_BLOCK  = 16;   // 256 threads / block
constexpr int BLOCK_THREADS    = THREADS_PER_NODE * NODES_PER_BLOCK;

__device__ __forceinline__ float4 fmax4(float4 a, float4 b) {
    return make_float4(fmaxf(a.x, b.x), fmaxf(a.y, b.y),
                       fmaxf(a.z, b.z), fmaxf(a.w, b.w));
}

__global__ __launch_bounds__(BLOCK_THREADS, 7)   // cap ~36 regs -> 56 warps/SM
void pool_max_kernel(const float* __restrict__ x,
                     const int* __restrict__ index,
                     float* __restrict__ out)
{
    const int lane  = threadIdx.x & (THREADS_PER_NODE - 1);
    const int group = threadIdx.x >> 4;
    const int node  = blockIdx.x * NODES_PER_BLOCK + group;   // grid.x*16 == N exactly
    const int batch = blockIdx.y;

    // Row pointer pre-biased by this lane's column quad: gather = base + idx*64.
    const float* __restrict__ xb = x + (size_t)batch * (N_NODES * HID) + lane * 4;

    // Hoist ALL 16 neighbor indices before the first gather (4 x int4 broadcast,
    // L1-hit). No dependent index load interrupts the gather request stream.
    const int4* __restrict__ idx4 = (const int4*)(index + node * M_NEIGH);
    int4 iv[4];
    #pragma unroll
    for (int c = 0; c < 4; c++) iv[c] = __ldg(idx4 + c);

    float4 acc = make_float4(-CUDART_INF_F, -CUDART_INF_F, -CUDART_INF_F, -CUDART_INF_F);
    const float4 zero4 = make_float4(0.f, 0.f, 0.f, 0.f);

    #pragma unroll
    for (int c = 0; c < 4; c++) {
        const int ids[4] = { iv[c].x, iv[c].y, iv[c].z, iv[c].w };

        #pragma unroll
        for (int j = 0; j < 4; j++) {
            const int idx = ids[j];
            // Unsigned compare: the N_NODES sentinel (and anything unexpected)
            // takes the zero-row path -> no OOB possible.
            const bool valid = ((unsigned)idx < (unsigned)N_NODES);
            const float4 v = valid ? __ldg((const float4*)(xb + (unsigned)idx * HID))
                                   : zero4;
            acc = fmax4(acc, v);
        }
    }

    // Streaming store: evict-first so the output stream doesn't displace the
    // L2-resident x working set (reduces gather misses to DRAM).
    const size_t obase = (size_t)batch * (N_NODES * HID)
                       + (unsigned)node * HID + (unsigned)lane * 4;
    __stcs((float4*)(out + obase), acc);
}

extern "C" void kernel_launch(void* const* d_in, const int* in_sizes, int n_in,
                              void* d_out, int out_size)
{
    const float* x     = (const float*)d_in[0];  // (4, 50000, 64) fp32
    const int*   index = (const int*)d_in[1];    // (50000, 16) int32
    float*       out   = (float*)d_out;          // (4, 50000, 64) fp32

    dim3 grid(N_NODES / NODES_PER_BLOCK, 4);     // 3125 x 4, exact cover
    pool_max_kernel<<<grid, BLOCK_THREADS>>>(x, index, out);
}

// round 12
// speedup vs baseline: 1.0410x; 1.0410x over previous
#include <cuda_runtime.h>
#include <math_constants.h>

// Pooling_21577915695109: out[b,n,:] = max over m of x_pad[b, index[n,m], :]
// x: (4, 50000, 64) fp32, index: (50000, 16) int32 in [0, 50000]; idx==50000 -> zero row.
//
// R11 (final shape): R6 base — batch on blockIdx.y, 16-lane row groups, SHFL
// index broadcast, 32-bit gather offsets (32 regs -> 8 blocks/SM, occ ~88%).
// Structural analysis: the kernel is L2 line-rate bound (6.4M irreducible 128B
// line requests over 184 LTS slices ~= the measured 77% L2 SOL); no data-path
// restructuring can reduce the line count. Micro-cleanups only:
//   - neighbor m=0 folds directly into the accumulator (no -INF init layer)
//   - streaming output store (__stcs): lowest measured DRAM%, protects x in L2.

constexpr int N_NODES = 50000;
constexpr int M_NEIGH = 16;
constexpr int HID     = 64;

constexpr int THREADS_PER_NODE = 16;   // 16 lanes x float4 = 64 floats = one row
constexpr int NODES_PER_BLOCK  = 16;   // 256 threads / block
constexpr int BLOCK_THREADS    = THREADS_PER_NODE * NODES_PER_BLOCK;

__device__ __forceinline__ float4 fmax4(float4 a, float4 b) {
    return make_float4(fmaxf(a.x, b.x), fmaxf(a.y, b.y),
                       fmaxf(a.z, b.z), fmaxf(a.w, b.w));
}

__global__ __launch_bounds__(BLOCK_THREADS, 8)   // pin <=32 regs -> 8 blocks/SM
void pool_max_kernel(const float* __restrict__ x,
                     const int* __restrict__ index,
                     float* __restrict__ out)
{
    const int lane  = threadIdx.x & (THREADS_PER_NODE - 1);
    const int group = threadIdx.x >> 4;
    const int node  = blockIdx.x * NODES_PER_BLOCK + group;   // grid.x*16 == N exactly
    const int batch = blockIdx.y;

    // Row pointer pre-biased by this lane's column quad: gather = base + idx*64.
    const float* __restrict__ xb = x + (size_t)batch * (N_NODES * HID) + lane * 4;

    // Lane l holds neighbor index l (coalesced 64B load per group), broadcast
    // within the 16-lane segment per m-step.
    const int my_idx = __ldg(&index[node * M_NEIGH + lane]);

    const float4 zero4 = make_float4(0.f, 0.f, 0.f, 0.f);

    // m = 0 folds straight into the accumulator (no -INF init, one less max).
    float4 acc;
    {
        const int idx = __shfl_sync(0xFFFFFFFFu, my_idx, 0, THREADS_PER_NODE);
        const bool valid = ((unsigned)idx < (unsigned)N_NODES);
        acc = valid ? __ldg((const float4*)(xb + (unsigned)idx * HID)) : zero4;
    }

    #pragma unroll
    for (int m = 1; m < M_NEIGH; m++) {
        const int idx = __shfl_sync(0xFFFFFFFFu, my_idx, m, THREADS_PER_NODE);
        // Unsigned compare: the N_NODES sentinel (and anything unexpected)
        // takes the zero-row path -> no OOB possible.
        const bool valid = ((unsigned)idx < (unsigned)N_NODES);
        const float4 v = valid ? __ldg((const float4*)(xb + (unsigned)idx * HID))
                               : zero4;
        acc = fmax4(acc, v);
    }

    // Streaming store: evict-first so the 51 MB output stream doesn't displace
    // the L2-resident x working set.
    const size_t obase = (size_t)batch * (N_NODES * HID)
                       + (unsigned)node * HID + (unsigned)lane * 4;
    __stcs((float4*)(out + obase), acc);
}

extern "C" void kernel_launch(void* const* d_in, const int* in_sizes, int n_in,
                              void* d_out, int out_size)
{
    const float* x     = (const float*)d_in[0];  // (4, 50000, 64) fp32
    const int*   index = (const int*)d_in[1];    // (50000, 16) int32
    float*       out   = (float*)d_out;          // (4, 50000, 64) fp32

    dim3 grid(N_NODES / NODES_PER_BLOCK, 4);     // 3125 x 4, exact cover
    pool_max_kernel<<<grid, BLOCK_THREADS>>>(x, index, out);
}

// round 13
// speedup vs baseline: 1.0471x; 1.0059x over previous
#include <cuda_runtime.h>
#include <math_constants.h>

// Pooling_21577915695109: out[b,n,:] = max over m of x_pad[b, index[n,m], :]
// x: (4, 50000, 64) fp32, index: (50000, 16) int32 in [0, 50000]; idx==50000 -> zero row.
//
// CONVERGED (R6-R12): L2 line-rate bound. 3.2M random 256B row gathers = 6.4M
// irreducible 128B L2 line requests; measured L2 SOL pinned at ~78% across five
// orthogonal optimization levers (issue shape, MLP depth, L1-bypass, streaming
// stores, scheduling). Best shape: batch on blockIdx.y, 16-lane row groups,
// SHFL index broadcast, 32-bit offsets (32 regs -> 8 blocks/SM, occ ~88%),
// m=0 folded into the accumulator, evict-first output stores.

constexpr int N_NODES = 50000;
constexpr int M_NEIGH = 16;
constexpr int HID     = 64;

constexpr int THREADS_PER_NODE = 16;   // 16 lanes x float4 = 64 floats = one row
constexpr int NODES_PER_BLOCK  = 16;   // 256 threads / block
constexpr int BLOCK_THREADS    = THREADS_PER_NODE * NODES_PER_BLOCK;

__device__ __forceinline__ float4 fmax4(float4 a, float4 b) {
    return make_float4(fmaxf(a.x, b.x), fmaxf(a.y, b.y),
                       fmaxf(a.z, b.z), fmaxf(a.w, b.w));
}

__global__ __launch_bounds__(BLOCK_THREADS, 8)   // pin <=32 regs -> 8 blocks/SM
void pool_max_kernel(const float* __restrict__ x,
                     const int* __restrict__ index,
                     float* __restrict__ out)
{
    const int lane  = threadIdx.x & (THREADS_PER_NODE - 1);
    const int group = threadIdx.x >> 4;
    const int node  = blockIdx.x * NODES_PER_BLOCK + group;   // grid.x*16 == N exactly
    const int batch = blockIdx.y;

    // Row pointer pre-biased by this lane's column quad: gather = base + idx*64.
    const float* __restrict__ xb = x + (size_t)batch * (N_NODES * HID) + lane * 4;

    // Lane l holds neighbor index l (coalesced 64B load per group), broadcast
    // within the 16-lane segment per m-step.
    const int my_idx = __ldg(&index[node * M_NEIGH + lane]);

    const float4 zero4 = make_float4(0.f, 0.f, 0.f, 0.f);

    // m = 0 folds straight into the accumulator (no -INF init, one less max).
    float4 acc;
    {
        const int idx = __shfl_sync(0xFFFFFFFFu, my_idx, 0, THREADS_PER_NODE);
        const bool valid = ((unsigned)idx < (unsigned)N_NODES);
        acc = valid ? __ldg((const float4*)(xb + (unsigned)idx * HID)) : zero4;
    }

    #pragma unroll
    for (int m = 1; m < M_NEIGH; m++) {
        const int idx = __shfl_sync(0xFFFFFFFFu, my_idx, m, THREADS_PER_NODE);
        // Unsigned compare: the N_NODES sentinel (and anything unexpected)
        // takes the zero-row path -> no OOB possible.
        const bool valid = ((unsigned)idx < (unsigned)N_NODES);
        const float4 v = valid ? __ldg((const float4*)(xb + (unsigned)idx * HID))
                               : zero4;
        acc = fmax4(acc, v);
    }

    // Streaming store: evict-first so the 51 MB output stream doesn't displace
    // the L2-resident x working set.
    const size_t obase = (size_t)batch * (N_NODES * HID)
                       + (unsigned)node * HID + (unsigned)lane * 4;
    __stcs((float4*)(out + obase), acc);
}

extern "C" void kernel_launch(void* const* d_in, const int* in_sizes, int n_in,
                              void* d_out, int out_size)
{
    const float* x     = (const float*)d_in[0];  // (4, 50000, 64) fp32
    const int*   index = (const int*)d_in[1];    // (50000, 16) int32
    float*       out   = (float*)d_out;          // (4, 50000, 64) fp32

    dim3 grid(N_NODES / NODES_PER_BLOCK, 4);     // 3125 x 4, exact cover
    pool_max_kernel<<<grid, BLOCK_THREADS>>>(x, index, out);
}

// round 14
// speedup vs baseline: 1.0479x; 1.0007x over previous
#include <cuda_runtime.h>
#include <math_constants.h>

// Pooling_21577915695109: out[b,n,:] = max over m of x_pad[b, index[n,m], :]
// x: (4, 50000, 64) fp32, index: (50000, 16) int32 in [0, 50000]; idx==50000 -> zero row.
//
// CONVERGED OPTIMUM (R6-R13): L2 line-rate bound. 3.2M random 256B row gathers
// = 6.4M irreducible 128B L2 line requests; L2 SOL pinned at ~78% across five
// orthogonal levers (issue shape, MLP depth, L1-bypass, streaming stores,
// scheduling; kernel-time spread 42.8-45.5us). Best shape: batch on blockIdx.y,
// 16-lane row groups, SHFL index broadcast, 32-bit offsets (32 regs -> 8
// blocks/SM, occ ~88%), m=0 folded into the accumulator, evict-first stores.

constexpr int N_NODES = 50000;
constexpr int M_NEIGH = 16;
constexpr int HID     = 64;

constexpr int THREADS_PER_NODE = 16;   // 16 lanes x float4 = 64 floats = one row
constexpr int NODES_PER_BLOCK  = 16;   // 256 threads / block
constexpr int BLOCK_THREADS    = THREADS_PER_NODE * NODES_PER_BLOCK;

__device__ __forceinline__ float4 fmax4(float4 a, float4 b) {
    return make_float4(fmaxf(a.x, b.x), fmaxf(a.y, b.y),
                       fmaxf(a.z, b.z), fmaxf(a.w, b.w));
}

__global__ __launch_bounds__(BLOCK_THREADS, 8)   // pin <=32 regs -> 8 blocks/SM
void pool_max_kernel(const float* __restrict__ x,
                     const int* __restrict__ index,
                     float* __restrict__ out)
{
    const int lane  = threadIdx.x & (THREADS_PER_NODE - 1);
    const int group = threadIdx.x >> 4;
    const int node  = blockIdx.x * NODES_PER_BLOCK + group;   // grid.x*16 == N exactly
    const int batch = blockIdx.y;

    // Row pointer pre-biased by this lane's column quad: gather = base + idx*64.
    const float* __restrict__ xb = x + (size_t)batch * (N_NODES * HID) + lane * 4;

    // Lane l holds neighbor index l (coalesced 64B load per group), broadcast
    // within the 16-lane segment per m-step.
    const int my_idx = __ldg(&index[node * M_NEIGH + lane]);

    const float4 zero4 = make_float4(0.f, 0.f, 0.f, 0.f);

    // m = 0 folds straight into the accumulator (no -INF init, one less max).
    float4 acc;
    {
        const int idx = __shfl_sync(0xFFFFFFFFu, my_idx, 0, THREADS_PER_NODE);
        const bool valid = ((unsigned)idx < (unsigned)N_NODES);
        acc = valid ? __ldg((const float4*)(xb + (unsigned)idx * HID)) : zero4;
    }

    #pragma unroll
    for (int m = 1; m < M_NEIGH; m++) {
        const int idx = __shfl_sync(0xFFFFFFFFu, my_idx, m, THREADS_PER_NODE);
        // Unsigned compare: the N_NODES sentinel (and anything unexpected)
        // takes the zero-row path -> no OOB possible.
        const bool valid = ((unsigned)idx < (unsigned)N_NODES);
        const float4 v = valid ? __ldg((const float4*)(xb + (unsigned)idx * HID))
                               : zero4;
        acc = fmax4(acc, v);
    }

    // Streaming store: evict-first so the 51 MB output stream doesn't displace
    // the L2-resident x working set.
    const size_t obase = (size_t)batch * (N_NODES * HID)
                       + (unsigned)node * HID + (unsigned)lane * 4;
    __stcs((float4*)(out + obase), acc);
}

extern "C" void kernel_launch(void* const* d_in, const int* in_sizes, int n_in,
                              void* d_out, int out_size)
{
    const float* x     = (const float*)d_in[0];  // (4, 50000, 64) fp32
    const int*   index = (const int*)d_in[1];    // (50000, 16) int32
    float*       out   = (float*)d_out;          // (4, 50000, 64) fp32

    dim3 grid(N_NODES / NODES_PER_BLOCK, 4);     // 3125 x 4, exact cover
    pool_max_kernel<<<grid, BLOCK_THREADS>>>(x, index, out);
}

// round 15
// speedup vs baseline: 1.0564x; 1.0082x over previous
#include <cuda_runtime.h>
#include <math_constants.h>

// Pooling_21577915695109: out[b,n,:] = max over m of x_pad[b, index[n,m], :]
// x: (4, 50000, 64) fp32, index: (50000, 16) int32 in [0, 50000]; idx==50000 -> zero row.
//
// FINAL CONVERGED OPTIMUM (R6-R14): L2 line-rate bound. 3.2M random 256B row
// gathers = 6.4M irreducible 128B L2 line requests; L2 SOL pinned at ~78%
// across five orthogonal levers (issue shape, MLP depth, L1-bypass, streaming
// stores, scheduling). Four consecutive confirmation runs within +-0.3us.
// Shape: batch on blockIdx.y, 16-lane row groups, SHFL index broadcast, 32-bit
// offsets (32 regs -> 8 blocks/SM, occ ~88%), m=0 folded into the accumulator,
// evict-first output stores.

constexpr int N_NODES = 50000;
constexpr int M_NEIGH = 16;
constexpr int HID     = 64;

constexpr int THREADS_PER_NODE = 16;   // 16 lanes x float4 = 64 floats = one row
constexpr int NODES_PER_BLOCK  = 16;   // 256 threads / block
constexpr int BLOCK_THREADS    = THREADS_PER_NODE * NODES_PER_BLOCK;

__device__ __forceinline__ float4 fmax4(float4 a, float4 b) {
    return make_float4(fmaxf(a.x, b.x), fmaxf(a.y, b.y),
                       fmaxf(a.z, b.z), fmaxf(a.w, b.w));
}

__global__ __launch_bounds__(BLOCK_THREADS, 8)   // pin <=32 regs -> 8 blocks/SM
void pool_max_kernel(const float* __restrict__ x,
                     const int* __restrict__ index,
                     float* __restrict__ out)
{
    const int lane  = threadIdx.x & (THREADS_PER_NODE - 1);
    const int group = threadIdx.x >> 4;
    const int node  = blockIdx.x * NODES_PER_BLOCK + group;   // grid.x*16 == N exactly
    const int batch = blockIdx.y;

    // Row pointer pre-biased by this lane's column quad: gather = base + idx*64.
    const float* __restrict__ xb = x + (size_t)batch * (N_NODES * HID) + lane * 4;

    // Lane l holds neighbor index l (coalesced 64B load per group), broadcast
    // within the 16-lane segment per m-step.
    const int my_idx = __ldg(&index[node * M_NEIGH + lane]);

    const float4 zero4 = make_float4(0.f, 0.f, 0.f, 0.f);

    // m = 0 folds straight into the accumulator (no -INF init, one less max).
    float4 acc;
    {
        const int idx = __shfl_sync(0xFFFFFFFFu, my_idx, 0, THREADS_PER_NODE);
        const bool valid = ((unsigned)idx < (unsigned)N_NODES);
        acc = valid ? __ldg((const float4*)(xb + (unsigned)idx * HID)) : zero4;
    }

    #pragma unroll
    for (int m = 1; m < M_NEIGH; m++) {
        const int idx = __shfl_sync(0xFFFFFFFFu, my_idx, m, THREADS_PER_NODE);
        // Unsigned compare: the N_NODES sentinel (and anything unexpected)
        // takes the zero-row path -> no OOB possible.
        const bool valid = ((unsigned)idx < (unsigned)N_NODES);
        const float4 v = valid ? __ldg((const float4*)(xb + (unsigned)idx * HID))
                               : zero4;
        acc = fmax4(acc, v);
    }

    // Streaming store: evict-first so the 51 MB output stream doesn't displace
    // the L2-resident x working set.
    const size_t obase = (size_t)batch * (N_NODES * HID)
                       + (unsigned)node * HID + (unsigned)lane * 4;
    __stcs((float4*)(out + obase), acc);
}

extern "C" void kernel_launch(void* const* d_in, const int* in_sizes, int n_in,
                              void* d_out, int out_size)
{
    const float* x     = (const float*)d_in[0];  // (4, 50000, 64) fp32
    const int*   index = (const int*)d_in[1];    // (50000, 16) int32
    float*       out   = (float*)d_out;          // (4, 50000, 64) fp32

    dim3 grid(N_NODES / NODES_PER_BLOCK, 4);     // 3125 x 4, exact cover
    pool_max_kernel<<<grid, BLOCK_THREADS>>>(x, index, out);
}